// round 11
// baseline (speedup 1.0000x reference)
#include <cuda_runtime.h>
#include <cuda_fp16.h>
#include <math.h>

#define N_NODES   100000
#define E_EDGES   1600000
#define W_IN      256
#define W_OUT     128
#define NUM_TYPES 4
#define K_STEPS   10
#define ALPHA_F   0.1f
#define EPS_F     1e-12f
#define TOTAL_NNZ (E_EDGES + N_NODES)
#define SCAN_B    256
#define NB_SCAN   ((N_NODES + SCAN_B - 1) / SCAN_B)   // 391

#define GB_NODES  64
#define GEMM_BLOCKS ((N_NODES + GB_NODES - 1) / GB_NODES)   // 1563
#define DEG_BLOCKS  ((E_EDGES + 255) / 256)                  // 6250
#define ST_BLOCKS   1184
#define TILDE_BLOCKS ((N_NODES + 7) / 8)                     // 12500
#define APPNP_BLOCKS ((N_NODES + 7) / 8)                     // 12500
#define LOSS_BLOCKS  ((2 * E_EDGES) / 256)                   // 12500

// ---------------- scratch (device globals; no allocation) ----------------
__device__ float    d_H[N_NODES * W_OUT];       // fp32 encoder output
__device__ __half   d_t16[N_NODES * W_OUT];     // tilde_H fp16
__device__ unsigned d_z8[N_NODES * 32];         // l2norm(tilde_H) int8 packed (128B/row)
__device__ __half   d_hA16[N_NODES * W_OUT];
__device__ __half   d_hB16[N_NODES * W_OUT];
__device__ int      d_deg[N_NODES];
__device__ int      d_cursor[N_NODES];
__device__ int      d_rowptr[N_NODES + 1];
__device__ int      d_bsum[NB_SCAN];
__device__ int      d_boff[NB_SCAN];
__device__ float    d_dinv[N_NODES];
__device__ int2     d_cv[TOTAL_NNZ];            // interleaved (col, val-bits)
__device__ float    d_tsum[NUM_TYPES * W_OUT];
__device__ float    d_tsq[NUM_TYPES * W_OUT];
__device__ float    d_tcnt[NUM_TYPES];
__device__ float    d_mean[NUM_TYPES * W_OUT];
__device__ float    d_std[NUM_TYPES * W_OUT];
__device__ double   d_posAcc;
__device__ double   d_negAcc;

// ---------------- init (runs every launch; graph-replay safe) ----------------
__global__ void init_kernel() {
    int i = blockIdx.x * blockDim.x + threadIdx.x;
    if (i < N_NODES) { d_deg[i] = 1; d_cursor[i] = 0; }   // self loop pre-counted
    if (i < NUM_TYPES * W_OUT) { d_tsum[i] = 0.f; d_tsq[i] = 0.f; }
    if (i < NUM_TYPES) d_tcnt[i] = 0.f;
    if (i == 0) { d_posAcc = 0.0; d_negAcc = 0.0; }
}

// ---------------- fused GEMM(+l2norm) + degree histogram ----------------
#define GB_CHUNK 32
__global__ void gemm_deg_kernel(const float* __restrict__ X,
                                const float* __restrict__ W,
                                const float* __restrict__ b,
                                const int* __restrict__ dst) {
    __shared__ float Ws[GB_CHUNK][W_OUT];
    __shared__ float Xs[GB_NODES][GB_CHUNK + 1];
    int tid = threadIdx.x;

    if (blockIdx.x >= GEMM_BLOCKS) {
        // ---- degree histogram blocks ----
        int e = (blockIdx.x - GEMM_BLOCKS) * 256 + tid;
        if (e < E_EDGES) atomicAdd(&d_deg[dst[e]], 1);
        return;
    }

    int fg  = tid & 31;
    int ng  = tid >> 5;
    int nodeBase = blockIdx.x * GB_NODES;

    unsigned long long accp[8][2];
#pragma unroll
    for (int i = 0; i < 8; i++) { accp[i][0] = 0ull; accp[i][1] = 0ull; }

    for (int kc = 0; kc < W_IN; kc += GB_CHUNK) {
#pragma unroll
        for (int j = 0; j < (GB_CHUNK * W_OUT) / 256; j++) {
            int idx = tid + j * 256;
            int kk = idx >> 7, ff = idx & 127;
            Ws[kk][ff] = W[(kc + kk) * W_OUT + ff];
        }
        {
            int kk = tid & 31;
            int r0 = tid >> 5;
#pragma unroll
            for (int j = 0; j < 8; j++) {
                int r = r0 + j * 8;
                int node = nodeBase + r;
                Xs[r][kk] = (node < N_NODES) ? X[node * W_IN + kc + kk] : 0.f;
            }
        }
        __syncthreads();
#pragma unroll
        for (int kk = 0; kk < GB_CHUNK; kk++) {
            float4 w4 = *reinterpret_cast<const float4*>(&Ws[kk][fg * 4]);
            unsigned long long wlo, whi;
            asm("mov.b64 %0, {%1, %2};" : "=l"(wlo) : "f"(w4.x), "f"(w4.y));
            asm("mov.b64 %0, {%1, %2};" : "=l"(whi) : "f"(w4.z), "f"(w4.w));
#pragma unroll
            for (int i = 0; i < 8; i++) {
                float x = Xs[ng + i * 8][kk];
                unsigned long long xx;
                asm("mov.b64 %0, {%1, %1};" : "=l"(xx) : "f"(x));
                asm("fma.rn.f32x2 %0, %1, %2, %0;" : "+l"(accp[i][0]) : "l"(xx), "l"(wlo));
                asm("fma.rn.f32x2 %0, %1, %2, %0;" : "+l"(accp[i][1]) : "l"(xx), "l"(whi));
            }
        }
        __syncthreads();
    }

    float4 b4 = *reinterpret_cast<const float4*>(&b[fg * 4]);
#pragma unroll
    for (int i = 0; i < 8; i++) {
        int node = nodeBase + ng + i * 8;
        float4 h;
        asm("mov.b64 {%0, %1}, %2;" : "=f"(h.x), "=f"(h.y) : "l"(accp[i][0]));
        asm("mov.b64 {%0, %1}, %2;" : "=f"(h.z), "=f"(h.w) : "l"(accp[i][1]));
        h.x += b4.x; h.y += b4.y; h.z += b4.z; h.w += b4.w;
        float ss = h.x * h.x + h.y * h.y + h.z * h.z + h.w * h.w;
#pragma unroll
        for (int off = 16; off; off >>= 1) ss += __shfl_xor_sync(0xffffffffu, ss, off);
        float inv = 1.f / fmaxf(sqrtf(ss), EPS_F);
        if (node < N_NODES) {
            h.x *= inv; h.y *= inv; h.z *= inv; h.w *= inv;
            *reinterpret_cast<float4*>(&d_H[node * W_OUT + fg * 4]) = h;
        }
    }
}

// ---------------- fused per-type stats + scan1 ----------------
__global__ void stats_scan1_kernel(const int* __restrict__ nt) {
    __shared__ float s_sum[NUM_TYPES * W_OUT];
    __shared__ float s_sq[NUM_TYPES * W_OUT];
    __shared__ float s_cnt[NUM_TYPES];
    __shared__ int s_scan[SCAN_B];
    int tid = threadIdx.x;

    if (blockIdx.x >= ST_BLOCKS) {
        // ---- scan1 blocks: per-block inclusive scan of deg -> local exclusive rowptr ----
        int bid = blockIdx.x - ST_BLOCKS;
        int i = bid * SCAN_B + tid;
        int v = (i < N_NODES) ? d_deg[i] : 0;
        s_scan[tid] = v;
        __syncthreads();
        for (int off = 1; off < SCAN_B; off <<= 1) {
            int t = (tid >= off) ? s_scan[tid - off] : 0;
            __syncthreads();
            s_scan[tid] += t;
            __syncthreads();
        }
        if (i < N_NODES) d_rowptr[i] = s_scan[tid] - v;
        if (tid == SCAN_B - 1) d_bsum[bid] = s_scan[SCAN_B - 1];
        return;
    }

    for (int i = tid; i < NUM_TYPES * W_OUT; i += 256) { s_sum[i] = 0.f; s_sq[i] = 0.f; }
    if (tid < NUM_TYPES) s_cnt[tid] = 0.f;
    __syncthreads();

    int lane = tid & 31;
    int gw = blockIdx.x * 8 + (tid >> 5);
    const int totalW = ST_BLOCKS * 8;

    float4 sum[NUM_TYPES], sq[NUM_TYPES];
    float cnt[NUM_TYPES];
#pragma unroll
    for (int t = 0; t < NUM_TYPES; t++) {
        sum[t] = make_float4(0.f, 0.f, 0.f, 0.f);
        sq[t]  = make_float4(0.f, 0.f, 0.f, 0.f);
        cnt[t] = 0.f;
    }

    for (int node = gw; node < N_NODES; node += 2 * totalW) {
        int n2 = node + totalW;
        bool has2 = n2 < N_NODES;
        int t0 = __ldg(&nt[node]);
        float4 h0 = *reinterpret_cast<const float4*>(&d_H[node * W_OUT + lane * 4]);
        int t1 = 0;
        float4 h1 = make_float4(0.f, 0.f, 0.f, 0.f);
        if (has2) {
            t1 = __ldg(&nt[n2]);
            h1 = *reinterpret_cast<const float4*>(&d_H[n2 * W_OUT + lane * 4]);
        }
#pragma unroll
        for (int tt = 0; tt < NUM_TYPES; tt++) {
            if (t0 == tt) {
                sum[tt].x += h0.x; sum[tt].y += h0.y; sum[tt].z += h0.z; sum[tt].w += h0.w;
                sq[tt].x += h0.x * h0.x; sq[tt].y += h0.y * h0.y;
                sq[tt].z += h0.z * h0.z; sq[tt].w += h0.w * h0.w;
                cnt[tt] += 1.f;
            }
            if (has2 && t1 == tt) {
                sum[tt].x += h1.x; sum[tt].y += h1.y; sum[tt].z += h1.z; sum[tt].w += h1.w;
                sq[tt].x += h1.x * h1.x; sq[tt].y += h1.y * h1.y;
                sq[tt].z += h1.z * h1.z; sq[tt].w += h1.w * h1.w;
                cnt[tt] += 1.f;
            }
        }
    }
#pragma unroll
    for (int tt = 0; tt < NUM_TYPES; tt++) {
        int fb = tt * W_OUT + lane * 4;
        atomicAdd(&s_sum[fb + 0], sum[tt].x); atomicAdd(&s_sum[fb + 1], sum[tt].y);
        atomicAdd(&s_sum[fb + 2], sum[tt].z); atomicAdd(&s_sum[fb + 3], sum[tt].w);
        atomicAdd(&s_sq[fb + 0], sq[tt].x);  atomicAdd(&s_sq[fb + 1], sq[tt].y);
        atomicAdd(&s_sq[fb + 2], sq[tt].z);  atomicAdd(&s_sq[fb + 3], sq[tt].w);
        if (lane == 0) atomicAdd(&s_cnt[tt], cnt[tt]);
    }
    __syncthreads();
    for (int i = tid; i < NUM_TYPES * W_OUT; i += 256) {
        atomicAdd(&d_tsum[i], s_sum[i]);
        atomicAdd(&d_tsq[i], s_sq[i]);
    }
    if (tid < NUM_TYPES) atomicAdd(&d_tcnt[tid], s_cnt[tid]);
}

// ---------------- fused finalize stats + scan2 ----------------
__global__ void finalize_scan2_kernel() {
    int tid = threadIdx.x;
    if (blockIdx.x < 2) {
        int i = blockIdx.x * 256 + tid;
        if (i < NUM_TYPES * W_OUT) {
            int t = i / W_OUT;
            float c = d_tcnt[t];
            float m = d_tsum[i] / c;
            float var = (d_tsq[i] - c * m * m) / (c - 1.f);
            d_mean[i] = m;
            d_std[i] = sqrtf(fmaxf(var, 0.f));
        }
    } else if (tid == 0) {
        int run = 0;
        for (int b = 0; b < NB_SCAN; b++) { d_boff[b] = run; run += d_bsum[b]; }
        d_rowptr[N_NODES] = run;
    }
}

// ---------------- fused tilde (fp16 + int8 z) + scan3 ----------------
__global__ void tilde_scan3_kernel(const int* __restrict__ nt) {
    if (blockIdx.x >= TILDE_BLOCKS) {
        int i = (blockIdx.x - TILDE_BLOCKS) * SCAN_B + threadIdx.x;
        if (i < N_NODES) {
            d_rowptr[i] += d_boff[i >> 8];
            d_dinv[i] = rsqrtf((float)d_deg[i]);
        }
        return;
    }
    int w = (blockIdx.x * blockDim.x + threadIdx.x) >> 5;
    int lane = threadIdx.x & 31;
    if (w >= N_NODES) return;
    int t = nt[w];
    float4 h = *reinterpret_cast<const float4*>(&d_H[w * W_OUT + lane * 4]);
    float4 m = *reinterpret_cast<const float4*>(&d_mean[t * W_OUT + lane * 4]);
    float4 s = *reinterpret_cast<const float4*>(&d_std[t * W_OUT + lane * 4]);
    float4 td;
    td.x = (h.x - m.x) / s.x; td.y = (h.y - m.y) / s.y;
    td.z = (h.z - m.z) / s.z; td.w = (h.w - m.w) / s.w;
    __half2 t0 = __floats2half2_rn(td.x, td.y);
    __half2 t1 = __floats2half2_rn(td.z, td.w);
    uint2 tp; tp.x = *reinterpret_cast<unsigned*>(&t0); tp.y = *reinterpret_cast<unsigned*>(&t1);
    reinterpret_cast<uint2*>(d_t16)[w * 32 + lane] = tp;

    float ss = td.x * td.x + td.y * td.y + td.z * td.z + td.w * td.w;
#pragma unroll
    for (int off = 16; off; off >>= 1) ss += __shfl_xor_sync(0xffffffffu, ss, off);
    float inv = 1.f / fmaxf(sqrtf(ss), EPS_F);
    int qx = __float2int_rn(td.x * inv * 127.f);
    int qy = __float2int_rn(td.y * inv * 127.f);
    int qz = __float2int_rn(td.z * inv * 127.f);
    int qw = __float2int_rn(td.w * inv * 127.f);
    unsigned qp = (qx & 255) | ((qy & 255) << 8) | ((qz & 255) << 16) | (qw << 24);
    d_z8[w * 32 + lane] = qp;
}

// ---------------- CSR fill (interleaved col/val) ----------------
__global__ void fill_kernel(const int* __restrict__ src, const int* __restrict__ dst) {
    int i = blockIdx.x * blockDim.x + threadIdx.x;
    if (i < E_EDGES) {
        int s = src[i], d = dst[i];
        int p = d_rowptr[d] + atomicAdd(&d_cursor[d], 1);
        d_cv[p] = make_int2(s, __float_as_int(d_dinv[s] * d_dinv[d]));
    } else if (i < E_EDGES + N_NODES) {
        int n = i - E_EDGES;
        int p = d_rowptr[n] + atomicAdd(&d_cursor[n], 1);
        float dv = d_dinv[n];
        d_cv[p] = make_int2(n, __float_as_int(dv * dv));
    }
}

// ---------------- APPNP machinery ----------------
__device__ __forceinline__ __half* buf16_ptr(int sel) {
    return sel == 0 ? d_t16 : (sel == 1 ? d_hA16 : d_hB16);
}

#define ACCUM(L, V) { \
    __half2 h0 = *reinterpret_cast<__half2*>(&L.x); \
    __half2 h1 = *reinterpret_cast<__half2*>(&L.y); \
    float2 f0 = __half22float2(h0); \
    float2 f1 = __half22float2(h1); \
    agg.x += (V) * f0.x; agg.y += (V) * f0.y; \
    agg.z += (V) * f1.x; agg.w += (V) * f1.y; }

__device__ __forceinline__ float4 appnp_gather(const uint2* __restrict__ hin,
                                               int w, int lane) {
    int start = d_rowptr[w], end = d_rowptr[w + 1];
    float4 agg = make_float4(0.f, 0.f, 0.f, 0.f);
    for (int base = start; base < end; base += 32) {
        int j = base + lane;
        int c = 0; float v = 0.f;
        if (j < end) {
            int2 e = __ldg(&d_cv[j]);
            c = e.x; v = __int_as_float(e.y);
        }
        int m = min(32, end - base);
        int k = 0;
        for (; k + 4 <= m; k += 4) {
            int cc0 = __shfl_sync(0xffffffffu, c, k + 0);
            int cc1 = __shfl_sync(0xffffffffu, c, k + 1);
            int cc2 = __shfl_sync(0xffffffffu, c, k + 2);
            int cc3 = __shfl_sync(0xffffffffu, c, k + 3);
            float v0 = __shfl_sync(0xffffffffu, v, k + 0);
            float v1 = __shfl_sync(0xffffffffu, v, k + 1);
            float v2 = __shfl_sync(0xffffffffu, v, k + 2);
            float v3 = __shfl_sync(0xffffffffu, v, k + 3);
            uint2 l0 = __ldg(&hin[cc0 * 32 + lane]);
            uint2 l1 = __ldg(&hin[cc1 * 32 + lane]);
            uint2 l2 = __ldg(&hin[cc2 * 32 + lane]);
            uint2 l3 = __ldg(&hin[cc3 * 32 + lane]);
            ACCUM(l0, v0) ACCUM(l1, v1) ACCUM(l2, v2) ACCUM(l3, v3)
        }
        for (; k < m; k++) {
            int cc = __shfl_sync(0xffffffffu, c, k);
            float vv = __shfl_sync(0xffffffffu, v, k);
            uint2 l = __ldg(&hin[cc * 32 + lane]);
            ACCUM(l, vv)
        }
    }
    return agg;
}

__device__ __forceinline__ void appnp_body(const uint2* __restrict__ hin,
                                           uint2* __restrict__ hout,
                                           int w, int lane) {
    float4 agg = appnp_gather(hin, w, lane);
    uint2 tp = reinterpret_cast<const uint2*>(d_t16)[w * 32 + lane];
    __half2 t0 = *reinterpret_cast<__half2*>(&tp.x);
    __half2 t1 = *reinterpret_cast<__half2*>(&tp.y);
    float2 tf0 = __half22float2(t0);
    float2 tf1 = __half22float2(t1);
    __half2 o0 = __floats2half2_rn((1.f - ALPHA_F) * agg.x + ALPHA_F * tf0.x,
                                   (1.f - ALPHA_F) * agg.y + ALPHA_F * tf0.y);
    __half2 o1 = __floats2half2_rn((1.f - ALPHA_F) * agg.z + ALPHA_F * tf1.x,
                                   (1.f - ALPHA_F) * agg.w + ALPHA_F * tf1.y);
    uint2 st; st.x = *reinterpret_cast<unsigned*>(&o0); st.y = *reinterpret_cast<unsigned*>(&o1);
    hout[w * 32 + lane] = st;
}

__global__ void __launch_bounds__(256, 6) appnp_kernel(int inSel, int outSel) {
    const uint2* __restrict__ hin = reinterpret_cast<const uint2*>(buf16_ptr(inSel));
    uint2* __restrict__ hout = reinterpret_cast<uint2*>(buf16_ptr(outSel));
    int w = (blockIdx.x * blockDim.x + threadIdx.x) >> 5;
    int lane = threadIdx.x & 31;
    if (w >= N_NODES) return;
    appnp_body(hin, hout, w, lane);
}

// ---------------- fused APPNP step 1 + contrastive loss ----------------
__global__ void __launch_bounds__(256, 6) appnp1_loss_kernel(const int* __restrict__ ei,
                                                             const int* __restrict__ ne) {
    __shared__ int s_a[256];
    __shared__ int s_b[256];
    __shared__ float s_wp[8], s_wn[8];
    int tid = threadIdx.x;

    if (blockIdx.x < APPNP_BLOCKS) {
        // ---- APPNP step 1: t16 -> hA ----
        const uint2* hin = reinterpret_cast<const uint2*>(d_t16);
        uint2* hout = reinterpret_cast<uint2*>(d_hA16);
        int w = (blockIdx.x * 256 + tid) >> 5;
        int lane = tid & 31;
        if (w >= N_NODES) return;
        appnp_body(hin, hout, w, lane);
        return;
    }

    // ---- loss blocks ----
    int blockBase = (blockIdx.x - APPNP_BLOCKS) * 256;
    int gid = blockBase + tid;
    {
        int a, b;
        if (gid < E_EDGES) { a = ei[gid]; b = ei[E_EDGES + gid]; }
        else { int e = gid - E_EDGES; a = ne[e]; b = ne[E_EDGES + e]; }
        s_a[tid] = a; s_b[tid] = b;
    }
    __syncthreads();

    int w = tid >> 5;
    int lane = tid & 31;
    int grp = lane >> 3;
    int sub = lane & 7;
    const uint4* __restrict__ z = reinterpret_cast<const uint4*>(d_z8);

    float accP = 0.f, accN = 0.f;
#pragma unroll
    for (int it = 0; it < 8; it++) {
        int slot = w * 32 + it * 4 + grp;
        int a = s_a[slot], b = s_b[slot];
        uint4 za = __ldg(&z[a * 8 + sub]);
        uint4 zb = __ldg(&z[b * 8 + sub]);
        int dot = 0;
        dot = __dp4a((int)za.x, (int)zb.x, dot);
        dot = __dp4a((int)za.y, (int)zb.y, dot);
        dot = __dp4a((int)za.z, (int)zb.z, dot);
        dot = __dp4a((int)za.w, (int)zb.w, dot);
#pragma unroll
        for (int off = 4; off; off >>= 1) dot += __shfl_xor_sync(0xffffffffu, dot, off);
        if (sub == 0) {
            float ds = (float)dot * (1.f / 16129.f);
            float ex = exp2f(ds * 0.72134752044f);   // exp(ds/2)
            if (blockBase + slot < E_EDGES) accP += ex; else accN += ex;
        }
    }
#pragma unroll
    for (int off = 16; off; off >>= 1) {
        accP += __shfl_xor_sync(0xffffffffu, accP, off);
        accN += __shfl_xor_sync(0xffffffffu, accN, off);
    }
    if (lane == 0) { s_wp[w] = accP; s_wn[w] = accN; }
    __syncthreads();
    if (tid == 0) {
        double p = 0.0, n = 0.0;
#pragma unroll
        for (int i = 0; i < 8; i++) { p += (double)s_wp[i]; n += (double)s_wn[i]; }
        if (p != 0.0) atomicAdd(&d_posAcc, p);
        if (n != 0.0) atomicAdd(&d_negAcc, n);
    }
}

// final step fused with renormalization: out = ((1-a)*agg + a*tilde) * std + mean (fp32)
__global__ void __launch_bounds__(256, 6) appnp_final_kernel(int inSel, const int* __restrict__ nt,
                                                             float* __restrict__ out) {
    const uint2* __restrict__ hin = reinterpret_cast<const uint2*>(buf16_ptr(inSel));
    int w = (blockIdx.x * blockDim.x + threadIdx.x) >> 5;
    int lane = threadIdx.x & 31;
    if (w >= N_NODES) return;
    float4 agg = appnp_gather(hin, w, lane);
    uint2 tp = reinterpret_cast<const uint2*>(d_t16)[w * 32 + lane];
    __half2 t0 = *reinterpret_cast<__half2*>(&tp.x);
    __half2 t1 = *reinterpret_cast<__half2*>(&tp.y);
    float2 tf0 = __half22float2(t0);
    float2 tf1 = __half22float2(t1);
    int t = nt[w];
    float4 m = *reinterpret_cast<const float4*>(&d_mean[t * W_OUT + lane * 4]);
    float4 s = *reinterpret_cast<const float4*>(&d_std[t * W_OUT + lane * 4]);
    float4 z;
    z.x = ((1.f - ALPHA_F) * agg.x + ALPHA_F * tf0.x) * s.x + m.x;
    z.y = ((1.f - ALPHA_F) * agg.y + ALPHA_F * tf0.y) * s.y + m.y;
    z.z = ((1.f - ALPHA_F) * agg.z + ALPHA_F * tf1.x) * s.z + m.z;
    z.w = ((1.f - ALPHA_F) * agg.w + ALPHA_F * tf1.y) * s.w + m.w;
    *reinterpret_cast<float4*>(&out[w * W_OUT + lane * 4]) = z;
}

__global__ void loss_final_kernel(float* __restrict__ out) {
    if (threadIdx.x == 0) {
        double pos = d_posAcc, neg = d_negAcc;
        out[N_NODES * W_OUT] = (float)(-log(pos / (pos + neg)));
    }
}

// ---------------- launch ----------------
extern "C" void kernel_launch(void* const* d_in, const int* in_sizes, int n_in,
                              void* d_out, int out_size) {
    const float* X  = (const float*)d_in[0];
    const float* W  = (const float*)d_in[1];
    const float* b  = (const float*)d_in[2];
    const int*   nt = (const int*)d_in[3];
    const int*   ei = (const int*)d_in[4];
    const int*   ne = (const int*)d_in[5];
    float* out = (float*)d_out;

    init_kernel<<<(N_NODES + 255) / 256, 256>>>();
    gemm_deg_kernel<<<GEMM_BLOCKS + DEG_BLOCKS, 256>>>(X, W, b, ei + E_EDGES);
    stats_scan1_kernel<<<ST_BLOCKS + NB_SCAN, 256>>>(nt);
    finalize_scan2_kernel<<<3, 256>>>();
    tilde_scan3_kernel<<<TILDE_BLOCKS + NB_SCAN, 256>>>(nt);
    fill_kernel<<<(E_EDGES + N_NODES + 255) / 256, 256>>>(ei, ei + E_EDGES);

    // APPNP step 1 (t16 -> hA) fused with loss
    appnp1_loss_kernel<<<APPNP_BLOCKS + LOSS_BLOCKS, 256>>>(ei, ne);

    // steps 2..9: ping-pong hA/hB; trace: 1->2, 2->1, ..., step9 ends in hA(1)
    int inSel = 1, outSel = 2;
    for (int k = 1; k < K_STEPS - 1; k++) {
        appnp_kernel<<<APPNP_BLOCKS, 256>>>(inSel, outSel);
        int t = inSel; inSel = outSel; outSel = t;
    }
    // after loop: steps 1..9 done, result of step 9 is in inSel
    appnp_final_kernel<<<APPNP_BLOCKS, 256>>>(inSel, nt, out);

    loss_final_kernel<<<1, 32>>>(out);
}

// round 13
// speedup vs baseline: 1.0373x; 1.0373x over previous
#include <cuda_runtime.h>
#include <cuda_fp16.h>
#include <math.h>

#define N_NODES   100000
#define E_EDGES   1600000
#define W_IN      256
#define W_OUT     128
#define NUM_TYPES 4
#define K_STEPS   10
#define ALPHA_F   0.1f
#define EPS_F     1e-12f
#define TOTAL_NNZ (E_EDGES + N_NODES)
#define SCAN_B    1024
#define NB_SCAN   ((N_NODES + SCAN_B - 1) / SCAN_B)

#define APPNP_BLOCKS ((N_NODES + 7) / 8)       // 12500
#define LOSS_BLOCKS  ((2 * E_EDGES) / 256)     // 12500

// ---------------- scratch (device globals; no allocation) ----------------
__device__ float    d_H[N_NODES * W_OUT];       // fp32 encoder output
__device__ __half   d_t16[N_NODES * W_OUT];     // tilde_H fp16
__device__ unsigned d_z8[N_NODES * 32];         // l2norm(tilde_H) int8 packed (128B/row)
__device__ __half   d_hA16[N_NODES * W_OUT];
__device__ __half   d_hB16[N_NODES * W_OUT];
__device__ int      d_deg[N_NODES];
__device__ int      d_cursor[N_NODES];
__device__ int      d_rowptr[N_NODES + 1];
__device__ int      d_bsum[NB_SCAN];
__device__ int      d_boff[NB_SCAN];
__device__ float    d_dinv[N_NODES];
__device__ int2     d_cv[TOTAL_NNZ];            // interleaved (col, val-bits)
__device__ float    d_tsum[NUM_TYPES * W_OUT];
__device__ float    d_tsq[NUM_TYPES * W_OUT];
__device__ float    d_tcnt[NUM_TYPES];
__device__ float    d_mean[NUM_TYPES * W_OUT];
__device__ float    d_std[NUM_TYPES * W_OUT];
__device__ double   d_posAcc;
__device__ double   d_negAcc;

// ---------------- init (runs every launch; graph-replay safe) ----------------
__global__ void init_kernel() {
    int i = blockIdx.x * blockDim.x + threadIdx.x;
    if (i < N_NODES) { d_deg[i] = 1; d_cursor[i] = 0; }   // self loop pre-counted
    if (i < NUM_TYPES * W_OUT) { d_tsum[i] = 0.f; d_tsq[i] = 0.f; }
    if (i < NUM_TYPES) d_tcnt[i] = 0.f;
    if (i == 0) { d_posAcc = 0.0; d_negAcc = 0.0; }
}

// ---------------- GEMM + bias + row l2norm -> H (fp32, packed FFMA2) ----------------
#define GB_NODES 64
#define GB_CHUNK 32
__global__ void gemm_l2norm_kernel(const float* __restrict__ X,
                                   const float* __restrict__ W,
                                   const float* __restrict__ b) {
    __shared__ float Ws[GB_CHUNK][W_OUT];
    __shared__ float Xs[GB_NODES][GB_CHUNK + 1];
    int tid = threadIdx.x;
    int fg  = tid & 31;
    int ng  = tid >> 5;
    int nodeBase = blockIdx.x * GB_NODES;

    unsigned long long accp[8][2];
#pragma unroll
    for (int i = 0; i < 8; i++) { accp[i][0] = 0ull; accp[i][1] = 0ull; }

    for (int kc = 0; kc < W_IN; kc += GB_CHUNK) {
#pragma unroll
        for (int j = 0; j < (GB_CHUNK * W_OUT) / 256; j++) {
            int idx = tid + j * 256;
            int kk = idx >> 7, ff = idx & 127;
            Ws[kk][ff] = W[(kc + kk) * W_OUT + ff];
        }
        {
            int kk = tid & 31;
            int r0 = tid >> 5;
#pragma unroll
            for (int j = 0; j < 8; j++) {
                int r = r0 + j * 8;
                int node = nodeBase + r;
                Xs[r][kk] = (node < N_NODES) ? X[node * W_IN + kc + kk] : 0.f;
            }
        }
        __syncthreads();
#pragma unroll
        for (int kk = 0; kk < GB_CHUNK; kk++) {
            float4 w4 = *reinterpret_cast<const float4*>(&Ws[kk][fg * 4]);
            unsigned long long wlo, whi;
            asm("mov.b64 %0, {%1, %2};" : "=l"(wlo) : "f"(w4.x), "f"(w4.y));
            asm("mov.b64 %0, {%1, %2};" : "=l"(whi) : "f"(w4.z), "f"(w4.w));
#pragma unroll
            for (int i = 0; i < 8; i++) {
                float x = Xs[ng + i * 8][kk];
                unsigned long long xx;
                asm("mov.b64 %0, {%1, %1};" : "=l"(xx) : "f"(x));
                asm("fma.rn.f32x2 %0, %1, %2, %0;" : "+l"(accp[i][0]) : "l"(xx), "l"(wlo));
                asm("fma.rn.f32x2 %0, %1, %2, %0;" : "+l"(accp[i][1]) : "l"(xx), "l"(whi));
            }
        }
        __syncthreads();
    }

    float4 b4 = *reinterpret_cast<const float4*>(&b[fg * 4]);
#pragma unroll
    for (int i = 0; i < 8; i++) {
        int node = nodeBase + ng + i * 8;
        float4 h;
        asm("mov.b64 {%0, %1}, %2;" : "=f"(h.x), "=f"(h.y) : "l"(accp[i][0]));
        asm("mov.b64 {%0, %1}, %2;" : "=f"(h.z), "=f"(h.w) : "l"(accp[i][1]));
        h.x += b4.x; h.y += b4.y; h.z += b4.z; h.w += b4.w;
        float ss = h.x * h.x + h.y * h.y + h.z * h.z + h.w * h.w;
#pragma unroll
        for (int off = 16; off; off >>= 1) ss += __shfl_xor_sync(0xffffffffu, ss, off);
        float inv = 1.f / fmaxf(sqrtf(ss), EPS_F);
        if (node < N_NODES) {
            h.x *= inv; h.y *= inv; h.z *= inv; h.w *= inv;
            *reinterpret_cast<float4*>(&d_H[node * W_OUT + fg * 4]) = h;
        }
    }
}

// ---------------- per-type stats (2-way ILP) ----------------
#define ST_BLOCKS 1184
__global__ void stats_kernel(const int* __restrict__ nt) {
    __shared__ float s_sum[NUM_TYPES * W_OUT];
    __shared__ float s_sq[NUM_TYPES * W_OUT];
    __shared__ float s_cnt[NUM_TYPES];
    int tid = threadIdx.x;
    for (int i = tid; i < NUM_TYPES * W_OUT; i += 256) { s_sum[i] = 0.f; s_sq[i] = 0.f; }
    if (tid < NUM_TYPES) s_cnt[tid] = 0.f;
    __syncthreads();

    int lane = tid & 31;
    int gw = blockIdx.x * 8 + (tid >> 5);
    const int totalW = ST_BLOCKS * 8;

    float4 sum[NUM_TYPES], sq[NUM_TYPES];
    float cnt[NUM_TYPES];
#pragma unroll
    for (int t = 0; t < NUM_TYPES; t++) {
        sum[t] = make_float4(0.f, 0.f, 0.f, 0.f);
        sq[t]  = make_float4(0.f, 0.f, 0.f, 0.f);
        cnt[t] = 0.f;
    }

    for (int node = gw; node < N_NODES; node += 2 * totalW) {
        int n2 = node + totalW;
        bool has2 = n2 < N_NODES;
        int t0 = __ldg(&nt[node]);
        float4 h0 = *reinterpret_cast<const float4*>(&d_H[node * W_OUT + lane * 4]);
        int t1 = 0;
        float4 h1 = make_float4(0.f, 0.f, 0.f, 0.f);
        if (has2) {
            t1 = __ldg(&nt[n2]);
            h1 = *reinterpret_cast<const float4*>(&d_H[n2 * W_OUT + lane * 4]);
        }
#pragma unroll
        for (int tt = 0; tt < NUM_TYPES; tt++) {
            if (t0 == tt) {
                sum[tt].x += h0.x; sum[tt].y += h0.y; sum[tt].z += h0.z; sum[tt].w += h0.w;
                sq[tt].x += h0.x * h0.x; sq[tt].y += h0.y * h0.y;
                sq[tt].z += h0.z * h0.z; sq[tt].w += h0.w * h0.w;
                cnt[tt] += 1.f;
            }
            if (has2 && t1 == tt) {
                sum[tt].x += h1.x; sum[tt].y += h1.y; sum[tt].z += h1.z; sum[tt].w += h1.w;
                sq[tt].x += h1.x * h1.x; sq[tt].y += h1.y * h1.y;
                sq[tt].z += h1.z * h1.z; sq[tt].w += h1.w * h1.w;
                cnt[tt] += 1.f;
            }
        }
    }
#pragma unroll
    for (int tt = 0; tt < NUM_TYPES; tt++) {
        int fb = tt * W_OUT + lane * 4;
        atomicAdd(&s_sum[fb + 0], sum[tt].x); atomicAdd(&s_sum[fb + 1], sum[tt].y);
        atomicAdd(&s_sum[fb + 2], sum[tt].z); atomicAdd(&s_sum[fb + 3], sum[tt].w);
        atomicAdd(&s_sq[fb + 0], sq[tt].x);  atomicAdd(&s_sq[fb + 1], sq[tt].y);
        atomicAdd(&s_sq[fb + 2], sq[tt].z);  atomicAdd(&s_sq[fb + 3], sq[tt].w);
        if (lane == 0) atomicAdd(&s_cnt[tt], cnt[tt]);
    }
    __syncthreads();
    for (int i = tid; i < NUM_TYPES * W_OUT; i += 256) {
        atomicAdd(&d_tsum[i], s_sum[i]);
        atomicAdd(&d_tsq[i], s_sq[i]);
    }
    if (tid < NUM_TYPES) atomicAdd(&d_tcnt[tid], s_cnt[tid]);
}

__global__ void finalize_stats_kernel() {
    int i = blockIdx.x * blockDim.x + threadIdx.x;
    if (i < NUM_TYPES * W_OUT) {
        int t = i / W_OUT;
        float c = d_tcnt[t];
        float m = d_tsum[i] / c;
        float var = (d_tsq[i] - c * m * m) / (c - 1.f);
        d_mean[i] = m;
        d_std[i] = sqrtf(fmaxf(var, 0.f));
    }
}

// ---------------- tilde_H (fp16) + z (int8 packed) ----------------
__global__ void tilde_kernel(const int* __restrict__ nt) {
    int w = (blockIdx.x * blockDim.x + threadIdx.x) >> 5;
    int lane = threadIdx.x & 31;
    if (w >= N_NODES) return;
    int t = nt[w];
    float4 h = *reinterpret_cast<const float4*>(&d_H[w * W_OUT + lane * 4]);
    float4 m = *reinterpret_cast<const float4*>(&d_mean[t * W_OUT + lane * 4]);
    float4 s = *reinterpret_cast<const float4*>(&d_std[t * W_OUT + lane * 4]);
    float4 td;
    td.x = (h.x - m.x) / s.x; td.y = (h.y - m.y) / s.y;
    td.z = (h.z - m.z) / s.z; td.w = (h.w - m.w) / s.w;
    __half2 t0 = __floats2half2_rn(td.x, td.y);
    __half2 t1 = __floats2half2_rn(td.z, td.w);
    uint2 tp; tp.x = *reinterpret_cast<unsigned*>(&t0); tp.y = *reinterpret_cast<unsigned*>(&t1);
    reinterpret_cast<uint2*>(d_t16)[w * 32 + lane] = tp;

    float ss = td.x * td.x + td.y * td.y + td.z * td.z + td.w * td.w;
#pragma unroll
    for (int off = 16; off; off >>= 1) ss += __shfl_xor_sync(0xffffffffu, ss, off);
    float inv = 1.f / fmaxf(sqrtf(ss), EPS_F);
    int qx = __float2int_rn(td.x * inv * 127.f);
    int qy = __float2int_rn(td.y * inv * 127.f);
    int qz = __float2int_rn(td.z * inv * 127.f);
    int qw = __float2int_rn(td.w * inv * 127.f);
    unsigned qp = (qx & 255) | ((qy & 255) << 8) | ((qz & 255) << 16) | (qw << 24);
    d_z8[w * 32 + lane] = qp;
}

// ---------------- degree histogram ----------------
__global__ void deg_kernel(const int* __restrict__ dst) {
    int e = blockIdx.x * blockDim.x + threadIdx.x;
    if (e < E_EDGES) atomicAdd(&d_deg[dst[e]], 1);
}

// ---------------- prefix scan -> rowptr ----------------
__global__ void scan1_kernel() {
    __shared__ int s[SCAN_B];
    int tid = threadIdx.x;
    int i = blockIdx.x * SCAN_B + tid;
    int v = (i < N_NODES) ? d_deg[i] : 0;
    s[tid] = v;
    __syncthreads();
    for (int off = 1; off < SCAN_B; off <<= 1) {
        int t = (tid >= off) ? s[tid - off] : 0;
        __syncthreads();
        s[tid] += t;
        __syncthreads();
    }
    if (i < N_NODES) d_rowptr[i] = s[tid] - v;
    if (tid == SCAN_B - 1) d_bsum[blockIdx.x] = s[SCAN_B - 1];
}

__global__ void scan2_kernel() {
    if (threadIdx.x == 0) {
        int run = 0;
        for (int b = 0; b < NB_SCAN; b++) { d_boff[b] = run; run += d_bsum[b]; }
        d_rowptr[N_NODES] = run;
    }
}

__global__ void scan3_kernel() {
    int i = blockIdx.x * blockDim.x + threadIdx.x;
    if (i < N_NODES) {
        d_rowptr[i] += d_boff[i >> 10];
        d_dinv[i] = rsqrtf((float)d_deg[i]);
    }
}

// ---------------- CSR fill (interleaved col/val) ----------------
__global__ void fill_kernel(const int* __restrict__ src, const int* __restrict__ dst) {
    int i = blockIdx.x * blockDim.x + threadIdx.x;
    if (i < E_EDGES) {
        int s = src[i], d = dst[i];
        int p = d_rowptr[d] + atomicAdd(&d_cursor[d], 1);
        d_cv[p] = make_int2(s, __float_as_int(d_dinv[s] * d_dinv[d]));
    } else if (i < E_EDGES + N_NODES) {
        int n = i - E_EDGES;
        int p = d_rowptr[n] + atomicAdd(&d_cursor[n], 1);
        float dv = d_dinv[n];
        d_cv[p] = make_int2(n, __float_as_int(dv * dv));
    }
}

// ---------------- APPNP machinery ----------------
__device__ __forceinline__ __half* buf16_ptr(int sel) {
    return sel == 0 ? d_t16 : (sel == 1 ? d_hA16 : d_hB16);
}

#define ACCUM(L, V) { \
    __half2 h0 = *reinterpret_cast<__half2*>(&L.x); \
    __half2 h1 = *reinterpret_cast<__half2*>(&L.y); \
    float2 f0 = __half22float2(h0); \
    float2 f1 = __half22float2(h1); \
    agg.x += (V) * f0.x; agg.y += (V) * f0.y; \
    agg.z += (V) * f1.x; agg.w += (V) * f1.y; }

__device__ __forceinline__ float4 appnp_gather(const uint2* __restrict__ hin,
                                               int w, int lane) {
    int start = d_rowptr[w], end = d_rowptr[w + 1];
    float4 agg = make_float4(0.f, 0.f, 0.f, 0.f);
    for (int base = start; base < end; base += 32) {
        int j = base + lane;
        int c = 0; float v = 0.f;
        if (j < end) {
            int2 e = __ldg(&d_cv[j]);
            c = e.x; v = __int_as_float(e.y);
        }
        int m = min(32, end - base);
        int k = 0;
        for (; k + 4 <= m; k += 4) {
            int cc0 = __shfl_sync(0xffffffffu, c, k + 0);
            int cc1 = __shfl_sync(0xffffffffu, c, k + 1);
            int cc2 = __shfl_sync(0xffffffffu, c, k + 2);
            int cc3 = __shfl_sync(0xffffffffu, c, k + 3);
            float v0 = __shfl_sync(0xffffffffu, v, k + 0);
            float v1 = __shfl_sync(0xffffffffu, v, k + 1);
            float v2 = __shfl_sync(0xffffffffu, v, k + 2);
            float v3 = __shfl_sync(0xffffffffu, v, k + 3);
            uint2 l0 = __ldg(&hin[cc0 * 32 + lane]);
            uint2 l1 = __ldg(&hin[cc1 * 32 + lane]);
            uint2 l2 = __ldg(&hin[cc2 * 32 + lane]);
            uint2 l3 = __ldg(&hin[cc3 * 32 + lane]);
            ACCUM(l0, v0) ACCUM(l1, v1) ACCUM(l2, v2) ACCUM(l3, v3)
        }
        for (; k < m; k++) {
            int cc = __shfl_sync(0xffffffffu, c, k);
            float vv = __shfl_sync(0xffffffffu, v, k);
            uint2 l = __ldg(&hin[cc * 32 + lane]);
            ACCUM(l, vv)
        }
    }
    return agg;
}

__device__ __forceinline__ void appnp_body(const uint2* __restrict__ hin,
                                           uint2* __restrict__ hout,
                                           int w, int lane) {
    float4 agg = appnp_gather(hin, w, lane);
    uint2 tp = reinterpret_cast<const uint2*>(d_t16)[w * 32 + lane];
    __half2 t0 = *reinterpret_cast<__half2*>(&tp.x);
    __half2 t1 = *reinterpret_cast<__half2*>(&tp.y);
    float2 tf0 = __half22float2(t0);
    float2 tf1 = __half22float2(t1);
    __half2 o0 = __floats2half2_rn((1.f - ALPHA_F) * agg.x + ALPHA_F * tf0.x,
                                   (1.f - ALPHA_F) * agg.y + ALPHA_F * tf0.y);
    __half2 o1 = __floats2half2_rn((1.f - ALPHA_F) * agg.z + ALPHA_F * tf1.x,
                                   (1.f - ALPHA_F) * agg.w + ALPHA_F * tf1.y);
    uint2 st; st.x = *reinterpret_cast<unsigned*>(&o0); st.y = *reinterpret_cast<unsigned*>(&o1);
    hout[w * 32 + lane] = st;
}

__global__ void __launch_bounds__(256, 6) appnp_kernel(int inSel, int outSel) {
    const uint2* __restrict__ hin = reinterpret_cast<const uint2*>(buf16_ptr(inSel));
    uint2* __restrict__ hout = reinterpret_cast<uint2*>(buf16_ptr(outSel));
    int w = (blockIdx.x * blockDim.x + threadIdx.x) >> 5;
    int lane = threadIdx.x & 31;
    if (w >= N_NODES) return;
    appnp_body(hin, hout, w, lane);
}

// ---------------- fused APPNP step 1 + contrastive loss ----------------
__global__ void __launch_bounds__(256, 6) appnp1_loss_kernel(const int* __restrict__ ei,
                                                             const int* __restrict__ ne) {
    __shared__ int s_a[256];
    __shared__ int s_b[256];
    __shared__ float s_wp[8], s_wn[8];
    int tid = threadIdx.x;

    if (blockIdx.x < APPNP_BLOCKS) {
        // ---- APPNP step 1: t16 -> hA ----
        const uint2* hin = reinterpret_cast<const uint2*>(d_t16);
        uint2* hout = reinterpret_cast<uint2*>(d_hA16);
        int w = (blockIdx.x * 256 + tid) >> 5;
        int lane = tid & 31;
        if (w >= N_NODES) return;
        appnp_body(hin, hout, w, lane);
        return;
    }

    // ---- loss blocks ----
    int blockBase = (blockIdx.x - APPNP_BLOCKS) * 256;
    int gid = blockBase + tid;
    {
        int a, b;
        if (gid < E_EDGES) { a = ei[gid]; b = ei[E_EDGES + gid]; }
        else { int e = gid - E_EDGES; a = ne[e]; b = ne[E_EDGES + e]; }
        s_a[tid] = a; s_b[tid] = b;
    }
    __syncthreads();

    int w = tid >> 5;
    int lane = tid & 31;
    int grp = lane >> 3;
    int sub = lane & 7;
    const uint4* __restrict__ z = reinterpret_cast<const uint4*>(d_z8);

    float accP = 0.f, accN = 0.f;
#pragma unroll
    for (int it = 0; it < 8; it++) {
        int slot = w * 32 + it * 4 + grp;
        int a = s_a[slot], b = s_b[slot];
        uint4 za = __ldg(&z[a * 8 + sub]);
        uint4 zb = __ldg(&z[b * 8 + sub]);
        int dot = 0;
        dot = __dp4a((int)za.x, (int)zb.x, dot);
        dot = __dp4a((int)za.y, (int)zb.y, dot);
        dot = __dp4a((int)za.z, (int)zb.z, dot);
        dot = __dp4a((int)za.w, (int)zb.w, dot);
#pragma unroll
        for (int off = 4; off; off >>= 1) dot += __shfl_xor_sync(0xffffffffu, dot, off);
        if (sub == 0) {
            float ds = (float)dot * (1.f / 16129.f);
            float ex = exp2f(ds * 0.72134752044f);   // exp(ds/2)
            if (blockBase + slot < E_EDGES) accP += ex; else accN += ex;
        }
    }
#pragma unroll
    for (int off = 16; off; off >>= 1) {
        accP += __shfl_xor_sync(0xffffffffu, accP, off);
        accN += __shfl_xor_sync(0xffffffffu, accN, off);
    }
    if (lane == 0) { s_wp[w] = accP; s_wn[w] = accN; }
    __syncthreads();
    if (tid == 0) {
        double p = 0.0, n = 0.0;
#pragma unroll
        for (int i = 0; i < 8; i++) { p += (double)s_wp[i]; n += (double)s_wn[i]; }
        if (p != 0.0) atomicAdd(&d_posAcc, p);
        if (n != 0.0) atomicAdd(&d_negAcc, n);
    }
}

// final APPNP step fused with renormalization + loss finalization
__global__ void __launch_bounds__(256, 6) appnp_final_kernel(int inSel, const int* __restrict__ nt,
                                                             float* __restrict__ out) {
    if (blockIdx.x >= APPNP_BLOCKS) {
        if (threadIdx.x == 0) {
            double pos = d_posAcc, neg = d_negAcc;
            out[N_NODES * W_OUT] = (float)(-log(pos / (pos + neg)));
        }
        return;
    }
    const uint2* __restrict__ hin = reinterpret_cast<const uint2*>(buf16_ptr(inSel));
    int w = (blockIdx.x * blockDim.x + threadIdx.x) >> 5;
    int lane = threadIdx.x & 31;
    if (w >= N_NODES) return;
    float4 agg = appnp_gather(hin, w, lane);
    uint2 tp = reinterpret_cast<const uint2*>(d_t16)[w * 32 + lane];
    __half2 t0 = *reinterpret_cast<__half2*>(&tp.x);
    __half2 t1 = *reinterpret_cast<__half2*>(&tp.y);
    float2 tf0 = __half22float2(t0);
    float2 tf1 = __half22float2(t1);
    int t = nt[w];
    float4 m = *reinterpret_cast<const float4*>(&d_mean[t * W_OUT + lane * 4]);
    float4 s = *reinterpret_cast<const float4*>(&d_std[t * W_OUT + lane * 4]);
    float4 z;
    z.x = ((1.f - ALPHA_F) * agg.x + ALPHA_F * tf0.x) * s.x + m.x;
    z.y = ((1.f - ALPHA_F) * agg.y + ALPHA_F * tf0.y) * s.y + m.y;
    z.z = ((1.f - ALPHA_F) * agg.z + ALPHA_F * tf1.x) * s.z + m.z;
    z.w = ((1.f - ALPHA_F) * agg.w + ALPHA_F * tf1.y) * s.w + m.w;
    *reinterpret_cast<float4*>(&out[w * W_OUT + lane * 4]) = z;
}

// ---------------- launch ----------------
extern "C" void kernel_launch(void* const* d_in, const int* in_sizes, int n_in,
                              void* d_out, int out_size) {
    const float* X  = (const float*)d_in[0];
    const float* W  = (const float*)d_in[1];
    const float* b  = (const float*)d_in[2];
    const int*   nt = (const int*)d_in[3];
    const int*   ei = (const int*)d_in[4];
    const int*   ne = (const int*)d_in[5];
    float* out = (float*)d_out;

    init_kernel<<<(N_NODES + 255) / 256, 256>>>();
    gemm_l2norm_kernel<<<(N_NODES + GB_NODES - 1) / GB_NODES, 256>>>(X, W, b);
    deg_kernel<<<(E_EDGES + 255) / 256, 256>>>(ei + E_EDGES);
    stats_kernel<<<ST_BLOCKS, 256>>>(nt);
    finalize_stats_kernel<<<(NUM_TYPES * W_OUT + 127) / 128, 128>>>();
    tilde_kernel<<<(N_NODES + 7) / 8, 256>>>(nt);
    scan1_kernel<<<NB_SCAN, SCAN_B>>>();
    scan2_kernel<<<1, 32>>>();
    scan3_kernel<<<(N_NODES + 255) / 256, 256>>>();
    fill_kernel<<<(E_EDGES + N_NODES + 255) / 256, 256>>>(ei, ei + E_EDGES);

    // APPNP step 1 (t16 -> hA) fused with contrastive loss
    appnp1_loss_kernel<<<APPNP_BLOCKS + LOSS_BLOCKS, 256>>>(ei, ne);

    // steps 2..9: ping-pong hA/hB; k1:1->2, k2:2->1, ..., k8:2->1 -> result in hA(1)
    int inSel = 1, outSel = 2;
    for (int k = 1; k < K_STEPS - 1; k++) {
        appnp_kernel<<<APPNP_BLOCKS, 256>>>(inSel, outSel);
        int t = inSel; inSel = outSel; outSel = t;
    }
    // step 10 fused with renorm -> out, plus loss-final tail block
    appnp_final_kernel<<<APPNP_BLOCKS + 1, 256>>>(inSel, nt, out);
}